// round 16
// baseline (speedup 1.0000x reference)
#include <cuda_runtime.h>
#include <cuda_bf16.h>
#include <cuda_fp16.h>
#include <math.h>

#define Bn 64
#define Nn 1024
#define Dn 64
#define Mr 64          // query rows per CTA
#define NB 64          // key block per stage
#define THREADS 256
#define SA 72          // elem stride: 144B rows (mult of 16)
#define ESH 4.0f       // exp shift: e' = exp(s - ESH)

// ---- smem byte offsets ----
#define SM_SPART 0          // float[2][64]
#define SM_SINV  512        // float[64]
#define Q_HI     1024       // 64*144 = 9216
#define Q_LO     10240
#define STAGE0   19456      // per stage: K_HI(9216)+K_LO(9216)+V(9216)
#define STAGESZ  27648
#define SM_TOTAL 74752      // STAGE0 + 2*STAGESZ (3 CTAs/SM: 224.3KB)
// O-reduction overlay after loop: [2][64][68] floats = 34816 B
#define RED      Q_HI
#define RSTR     68

// ---- preconverted operand buffers ----
#define NELEM2 2097152      // 64*1024*64 / 2 (packed 16-bit pairs)
__device__ __align__(16) unsigned qhi_g[NELEM2];
__device__ __align__(16) unsigned qlo_g[NELEM2];
__device__ __align__(16) unsigned khi_g[NELEM2];
__device__ __align__(16) unsigned klo_g[NELEM2];
__device__ __align__(16) unsigned vh_g [NELEM2];

__device__ __forceinline__ void mma16816(float* c, const unsigned* a, const unsigned* b) {
    asm volatile(
        "mma.sync.aligned.m16n8k16.row.col.f32.bf16.bf16.f32 "
        "{%0,%1,%2,%3}, {%4,%5,%6,%7}, {%8,%9}, {%0,%1,%2,%3};"
        : "+f"(c[0]), "+f"(c[1]), "+f"(c[2]), "+f"(c[3])
        : "r"(a[0]), "r"(a[1]), "r"(a[2]), "r"(a[3]), "r"(b[0]), "r"(b[1]));
}
__device__ __forceinline__ void mma16816h(float* c, const unsigned* a, const unsigned* b) {
    asm volatile(
        "mma.sync.aligned.m16n8k16.row.col.f32.f16.f16.f32 "
        "{%0,%1,%2,%3}, {%4,%5,%6,%7}, {%8,%9}, {%0,%1,%2,%3};"
        : "+f"(c[0]), "+f"(c[1]), "+f"(c[2]), "+f"(c[3])
        : "r"(a[0]), "r"(a[1]), "r"(a[2]), "r"(a[3]), "r"(b[0]), "r"(b[1]));
}
__device__ __forceinline__ void ldsm4(unsigned* r, unsigned addr) {
    asm volatile("ldmatrix.sync.aligned.m8n8.x4.shared.b16 {%0,%1,%2,%3}, [%4];"
        : "=r"(r[0]), "=r"(r[1]), "=r"(r[2]), "=r"(r[3]) : "r"(addr));
}
__device__ __forceinline__ void ldsm4t(unsigned* r, unsigned addr) {
    asm volatile("ldmatrix.sync.aligned.m8n8.x4.trans.shared.b16 {%0,%1,%2,%3}, [%4];"
        : "=r"(r[0]), "=r"(r[1]), "=r"(r[2]), "=r"(r[3]) : "r"(addr));
}
__device__ __forceinline__ void cpa16(unsigned dst, const void* src) {
    asm volatile("cp.async.cg.shared.global [%0], [%1], 16;" :: "r"(dst), "l"(src));
}
#define CP_COMMIT() asm volatile("cp.async.commit_group;" ::: "memory")
#define CP_WAIT1()  asm volatile("cp.async.wait_group 1;"  ::: "memory")
__device__ __forceinline__ void gang_bar(int g) {
    asm volatile("bar.sync %0, %1;" :: "r"(g + 1), "r"(128) : "memory");
}

__device__ __forceinline__ void split4(float4 a, unsigned& h0, unsigned& h1,
                                       unsigned& l0, unsigned& l1) {
    __nv_bfloat162 H0 = __floats2bfloat162_rn(a.x, a.y);
    __nv_bfloat162 H1 = __floats2bfloat162_rn(a.z, a.w);
    float2 f0 = __bfloat1622float2(H0);
    float2 f1 = __bfloat1622float2(H1);
    __nv_bfloat162 L0 = __floats2bfloat162_rn(a.x - f0.x, a.y - f0.y);
    __nv_bfloat162 L1 = __floats2bfloat162_rn(a.z - f1.x, a.w - f1.y);
    h0 = *(unsigned*)&H0; h1 = *(unsigned*)&H1;
    l0 = *(unsigned*)&L0; l1 = *(unsigned*)&L1;
}

// ---- prep: fold adds + 1/8 scale (Q only) + precision split ----
__global__ __launch_bounds__(256)
void prep_kernel(const float* __restrict__ q, const float* __restrict__ qs,
                 const float* __restrict__ k, const float* __restrict__ ks,
                 const float* __restrict__ v)
{
    const int idx = (blockIdx.x * 256 + threadIdx.x) * 4;
    const int u = idx >> 1;
    {
        float4 a = *(const float4*)(q + idx);
        float4 s = *(const float4*)(qs + idx);
        a.x = (a.x + s.x) * 0.125f; a.y = (a.y + s.y) * 0.125f;
        a.z = (a.z + s.z) * 0.125f; a.w = (a.w + s.w) * 0.125f;
        unsigned h0, h1, l0, l1; split4(a, h0, h1, l0, l1);
        *(uint2*)&qhi_g[u] = make_uint2(h0, h1);
        *(uint2*)&qlo_g[u] = make_uint2(l0, l1);
    }
    {
        float4 a = *(const float4*)(k + idx);
        float4 s = *(const float4*)(ks + idx);
        a.x += s.x; a.y += s.y; a.z += s.z; a.w += s.w;
        unsigned h0, h1, l0, l1; split4(a, h0, h1, l0, l1);
        *(uint2*)&khi_g[u] = make_uint2(h0, h1);
        *(uint2*)&klo_g[u] = make_uint2(l0, l1);
    }
    {
        float4 x = *(const float4*)(v + idx);
        __half2 H0 = __floats2half2_rn(x.x, x.y);
        __half2 H1 = __floats2half2_rn(x.z, x.w);
        *(uint2*)&vh_g[u] = make_uint2(*(unsigned*)&H0, *(unsigned*)&H1);
    }
}

__global__ __launch_bounds__(THREADS, 3)
void sdpa_fused_kernel(float* __restrict__ out,
                       float* __restrict__ attn,
                       float* __restrict__ score)
{
    extern __shared__ char smb[];
    const unsigned sb = (unsigned)__cvta_generic_to_shared(smb);
    const int tid  = threadIdx.x;
    const int wid  = tid >> 5;
    const int lane = tid & 31;
    const int b    = blockIdx.y;
    const int row0 = blockIdx.x * Mr;
    const size_t bND = (size_t)b * Nn * Dn;
    const size_t bNN = (size_t)b * Nn * Nn;

    float* spart = (float*)(smb + SM_SPART);
    float* sinv  = (float*)(smb + SM_SINV);
    float* red   = (float*)(smb + RED);

    const int mq2 = wid >> 1;   // 0..3 : 16 query rows each
    const int nq  = wid & 1;    // 0..1 : gang id; 32 keys each
    const int lq = lane >> 2;   // 0..7
    const int lr = lane & 3;    // 0..3
    const int lt = ((wid >> 1) << 5) | lane;   // gang-local thread id 0..127

    float sreg[2] = {0.f, 0.f};
    float oacc[8][4];
    #pragma unroll
    for (int dn = 0; dn < 8; dn++)
        #pragma unroll
        for (int i = 0; i < 4; i++) oacc[dn][i] = 0.f;

    // ---- gang-owned fill chunks: 768 = 3 ops x 32 rows x 8 parts per gang ----
    unsigned dstoff[6];
    const unsigned* srcp[6];
    #pragma unroll
    for (int i = 0; i < 6; i++) {
        int c = lt + i * 128;                  // 0..767 within gang
        int op = c >> 8, pair = c & 255;       // op 0..2; pair over 32 rows x 8 parts
        int row = pair >> 3, part = pair & 7;
        dstoff[i] = (unsigned)(op * 9216 + (nq * 32 + row) * 144 + part * 16);
        const unsigned* base = (op == 0) ? khi_g : (op == 1) ? klo_g : vh_g;
        srcp[i] = base + (size_t)(b * Nn + nq * 32 + row) * 32 + part * 4;
    }
    auto fillS = [&](int sf) {
        const unsigned stK = sb + STAGE0 + (unsigned)sf * STAGESZ;
        #pragma unroll
        for (int i = 0; i < 6; i++) {
            cpa16(stK + dstoff[i], srcp[i]);
            srcp[i] += NB * 32;
        }
    };

    // ---- prologue: Q (1024 chunks, whole CTA) + stage0 (g0), stage1 (g1) ----
    #pragma unroll
    for (int i = 0; i < 4; i++) {
        int c = tid + i * 256;
        int op = c >> 9, rem = c & 511;
        int row = rem >> 3, part = rem & 7;
        unsigned d = sb + Q_HI + (unsigned)(op * 9216 + row * 144 + part * 16);
        const unsigned* s = (op ? qlo_g : qhi_g)
                          + (size_t)(b * Nn + row0 + row) * 32 + part * 4;
        cpa16(d, s);
    }
    fillS(0);
    CP_COMMIT();
    fillS(1);
    CP_COMMIT();
    CP_WAIT1();
    __syncthreads();

    const unsigned a_lane = (unsigned)(((lane & 15) * SA + (lane >> 4) * 8) * 2);
    const unsigned b_lane = (unsigned)(((((lane >> 4) << 3) + (lane & 7)) * SA
                                        + (((lane >> 3) & 1) << 3)) * 2);
    const unsigned aS0 = sb + Q_HI + (unsigned)((mq2 * 16) * SA * 2) + a_lane;
    const unsigned vb_lane = (unsigned)(((lane & 15) * SA + (lane >> 4) * 8) * 2);

    for (int kb = 0; kb < Nn / NB; kb++) {
        const unsigned stK = sb + STAGE0 + (unsigned)(kb & 1) * STAGESZ;

        // ---- S-GEMM: 16 rows x 32 keys (bf16 3-term), scores pre-scaled ----
        float acc[4][4];
        #pragma unroll
        for (int nf = 0; nf < 4; nf++)
            #pragma unroll
            for (int i = 0; i < 4; i++) acc[nf][i] = 0.f;

        const unsigned bS0 = stK + (unsigned)((nq * 32) * SA * 2) + b_lane;
        const unsigned bS1 = bS0 + (unsigned)(16 * SA * 2);
        #pragma unroll
        for (int ksi = 0; ksi < 4; ksi++) {
            const unsigned ko = (unsigned)(ksi * 32);
            unsigned ah[4], al[4], bh[8], bl[8];
            ldsm4(ah, aS0 + ko);
            ldsm4(al, aS0 + ko + (Q_LO - Q_HI));
            ldsm4(bh,     bS0 + ko);
            ldsm4(bh + 4, bS1 + ko);
            ldsm4(bl,     bS0 + ko + 9216);
            ldsm4(bl + 4, bS1 + ko + 9216);
            #pragma unroll
            for (int nf = 0; nf < 4; nf++) {
                mma16816(acc[nf], ah, bh + nf * 2);
                mma16816(acc[nf], ah, bl + nf * 2);
                mma16816(acc[nf], al, bh + nf * 2);
            }
        }

        // ---- exp -> E frags (fp16), row sums ----
        unsigned ahv[2][4];
        #pragma unroll
        for (int nf = 0; nf < 4; nf++) {
            float e0 = __expf(acc[nf][0] - ESH), e1 = __expf(acc[nf][1] - ESH);
            float e2 = __expf(acc[nf][2] - ESH), e3 = __expf(acc[nf][3] - ESH);
            sreg[0] += e0 + e1;
            sreg[1] += e2 + e3;
            __half2 ep0 = __floats2half2_rn(e0, e1);
            __half2 ep1 = __floats2half2_rn(e2, e3);
            const int kf = nf >> 1, pos = (nf & 1) * 2;
            ahv[kf][pos]     = *(unsigned*)&ep0;
            ahv[kf][pos + 1] = *(unsigned*)&ep1;
        }

        // ---- PV (fp16): 32 keys x 64 d-cols ----
        #pragma unroll
        for (int kf = 0; kf < 2; kf++) {
            const unsigned bVb = stK + 18432u
                + (unsigned)((nq * 32 + kf * 16) * SA * 2) + vb_lane;
            #pragma unroll
            for (int dn = 0; dn < 4; dn++) {
                unsigned bh[4];
                ldsm4t(bh, bVb + dn * 32);
                mma16816h(oacc[dn * 2 + 0], ahv[kf], bh + 0);
                mma16816h(oacc[dn * 2 + 1], ahv[kf], bh + 2);
            }
        }

        // ---- score STG last (drains behind MMA latency) ----
        #pragma unroll
        for (int nf = 0; nf < 4; nf++) {
            const int r0 = row0 + mq2 * 16 + lq;
            const int cc = kb * NB + nq * 32 + nf * 8 + lr * 2;
            float* g0 = score + bNN + (size_t)r0 * Nn + cc;
            *(float2*)g0 = make_float2(acc[nf][0], acc[nf][1]);
            *(float2*)(g0 + (size_t)8 * Nn) = make_float2(acc[nf][2], acc[nf][3]);
        }

        gang_bar(nq);      // gang's reads of its half of stage kb done
        if (kb + 2 < Nn / NB) fillS(kb & 1);
        CP_COMMIT();
        CP_WAIT1();        // this thread's fill(kb+1) half complete
        gang_bar(nq);      // whole gang's fill(kb+1) half complete
    }

    __syncthreads();       // both gangs out of loop (RED overlays Q region)

    // ---- combine row sums + stage partial O ----
    #pragma unroll
    for (int i = 0; i < 2; i++) {
        sreg[i] += __shfl_xor_sync(0xffffffffu, sreg[i], 1);
        sreg[i] += __shfl_xor_sync(0xffffffffu, sreg[i], 2);
    }
    if (lr == 0) {
        spart[nq * 64 + mq2 * 16 + lq]     = sreg[0];
        spart[nq * 64 + mq2 * 16 + 8 + lq] = sreg[1];
    }
    {
        const int rl = mq2 * 16 + lq;
        #pragma unroll
        for (int dn = 0; dn < 8; dn++) {
            const int cl = dn * 8 + 2 * lr;
            float* p0 = red + ((size_t)nq * 64 + rl) * RSTR + cl;
            *(float2*)p0 = make_float2(oacc[dn][0], oacc[dn][1]);
            *(float2*)(p0 + 8 * RSTR) = make_float2(oacc[dn][2], oacc[dn][3]);
        }
    }
    __syncthreads();

    // ---- reduce 2 slices, scale by 1/rowsum, write O; publish sinv ----
    {
        const int r = tid >> 2;
        const int cb = (tid & 3) * 16;
        const float iv = 1.0f / (spart[r] + spart[64 + r]);
        if ((tid & 3) == 0) sinv[r] = iv;
        float* orow = out + bND + (size_t)(row0 + r) * Dn;
        #pragma unroll
        for (int g = 0; g < 4; g++) {
            const int c = cb + g * 4;
            float4 s0 = *(float4*)(red + (size_t)r * RSTR + c);
            float4 s1 = *(float4*)(red + ((size_t)64 + r) * RSTR + c);
            float4 o;
            o.x = (s0.x + s1.x) * iv;
            o.y = (s0.y + s1.y) * iv;
            o.z = (s0.z + s1.z) * iv;
            o.w = (s0.w + s1.w) * iv;
            *(float4*)(orow + c) = o;
        }
    }
    __syncthreads();

    // ---- coalesced attn rescale: attn = exp(score - ESH) * inv ----
    #pragma unroll
    for (int rr = 0; rr < 8; rr++) {
        const int r = rr * 8 + wid;
        const float iv = sinv[r];
        const float* srow = score + bNN + (size_t)(row0 + r) * Nn;
        float* arow = attn + bNN + (size_t)(row0 + r) * Nn;
        #pragma unroll
        for (int j = 0; j < 8; j++) {
            float4 x = __ldcs((const float4*)(srow + j * 128 + lane * 4));
            float4 p;
            p.x = __expf(x.x - ESH) * iv; p.y = __expf(x.y - ESH) * iv;
            p.z = __expf(x.z - ESH) * iv; p.w = __expf(x.w - ESH) * iv;
            __stwt((float4*)(arow + j * 128 + lane * 4), p);
        }
    }
}

extern "C" void kernel_launch(void* const* d_in, const int* in_sizes, int n_in,
                              void* d_out, int out_size) {
    const float* q  = (const float*)d_in[0];
    const float* k  = (const float*)d_in[1];
    const float* v  = (const float*)d_in[2];
    const float* qs = (const float*)d_in[3];
    const float* ks = (const float*)d_in[4];

    float* out   = (float*)d_out;
    float* attn  = out  + (size_t)Bn * Nn * Dn;
    float* score = attn + (size_t)Bn * Nn * Nn;

    prep_kernel<<<(Bn * Nn * Dn) / (256 * 4), 256>>>(q, qs, k, ks, v);

    cudaFuncSetAttribute(sdpa_fused_kernel,
                         cudaFuncAttributeMaxDynamicSharedMemorySize, SM_TOTAL);
    dim3 grid(Nn / Mr, Bn);
    sdpa_fused_kernel<<<grid, THREADS, SM_TOTAL>>>(out, attn, score);
}

// round 17
// speedup vs baseline: 1.1477x; 1.1477x over previous
#include <cuda_runtime.h>
#include <cuda_bf16.h>
#include <cuda_fp16.h>
#include <math.h>

#define Bn 64
#define Nn 1024
#define Dn 64
#define Mr 64          // query rows per CTA
#define NB 64          // key block per stage
#define THREADS 256
#define SA 72          // elem stride: 144B rows (mult of 16)
#define ESH 4.0f       // exp shift: e' = exp(s - ESH)

// ---- smem byte offsets ----
#define SM_SPART 0          // float[2][64]
#define SM_SINV  512        // float[64]
#define Q_HI     1024       // 64*144 = 9216
#define Q_LO     10240
#define STAGE0   19456      // per stage: K_HI(9216)+K_LO(9216)+V(9216)
#define STAGESZ  27648
#define SM_TOTAL 74752      // STAGE0 + 2*STAGESZ (3 CTAs/SM: 224.3KB)
// O-reduction overlay after loop: [2][64][68] floats = 34816 B
#define RED      Q_HI
#define RSTR     68

// ---- preconverted operand buffers (K hi/lo bf16, V fp16) ----
#define NELEM2 2097152      // 64*1024*64 / 2 (packed 16-bit pairs)
__device__ __align__(16) unsigned khi_g[NELEM2];
__device__ __align__(16) unsigned klo_g[NELEM2];
__device__ __align__(16) unsigned vh_g [NELEM2];

__device__ __forceinline__ void mma16816(float* c, const unsigned* a, const unsigned* b) {
    asm volatile(
        "mma.sync.aligned.m16n8k16.row.col.f32.bf16.bf16.f32 "
        "{%0,%1,%2,%3}, {%4,%5,%6,%7}, {%8,%9}, {%0,%1,%2,%3};"
        : "+f"(c[0]), "+f"(c[1]), "+f"(c[2]), "+f"(c[3])
        : "r"(a[0]), "r"(a[1]), "r"(a[2]), "r"(a[3]), "r"(b[0]), "r"(b[1]));
}
__device__ __forceinline__ void mma16816h(float* c, const unsigned* a, const unsigned* b) {
    asm volatile(
        "mma.sync.aligned.m16n8k16.row.col.f32.f16.f16.f32 "
        "{%0,%1,%2,%3}, {%4,%5,%6,%7}, {%8,%9}, {%0,%1,%2,%3};"
        : "+f"(c[0]), "+f"(c[1]), "+f"(c[2]), "+f"(c[3])
        : "r"(a[0]), "r"(a[1]), "r"(a[2]), "r"(a[3]), "r"(b[0]), "r"(b[1]));
}
__device__ __forceinline__ void ldsm4(unsigned* r, unsigned addr) {
    asm volatile("ldmatrix.sync.aligned.m8n8.x4.shared.b16 {%0,%1,%2,%3}, [%4];"
        : "=r"(r[0]), "=r"(r[1]), "=r"(r[2]), "=r"(r[3]) : "r"(addr));
}
__device__ __forceinline__ void ldsm4t(unsigned* r, unsigned addr) {
    asm volatile("ldmatrix.sync.aligned.m8n8.x4.trans.shared.b16 {%0,%1,%2,%3}, [%4];"
        : "=r"(r[0]), "=r"(r[1]), "=r"(r[2]), "=r"(r[3]) : "r"(addr));
}
__device__ __forceinline__ void cpa16(unsigned dst, const void* src) {
    asm volatile("cp.async.cg.shared.global [%0], [%1], 16;" :: "r"(dst), "l"(src));
}
#define CP_COMMIT() asm volatile("cp.async.commit_group;" ::: "memory")
#define CP_WAIT1()  asm volatile("cp.async.wait_group 1;"  ::: "memory")

__device__ __forceinline__ void split4(float4 a, unsigned& h0, unsigned& h1,
                                       unsigned& l0, unsigned& l1) {
    __nv_bfloat162 H0 = __floats2bfloat162_rn(a.x, a.y);
    __nv_bfloat162 H1 = __floats2bfloat162_rn(a.z, a.w);
    float2 f0 = __bfloat1622float2(H0);
    float2 f1 = __bfloat1622float2(H1);
    __nv_bfloat162 L0 = __floats2bfloat162_rn(a.x - f0.x, a.y - f0.y);
    __nv_bfloat162 L1 = __floats2bfloat162_rn(a.z - f1.x, a.w - f1.y);
    h0 = *(unsigned*)&H0; h1 = *(unsigned*)&H1;
    l0 = *(unsigned*)&L0; l1 = *(unsigned*)&L1;
}

// ---- prep: K fold+split and V fp16 only (Q handled in main) ----
__global__ __launch_bounds__(256)
void prep_kernel(const float* __restrict__ k, const float* __restrict__ ks,
                 const float* __restrict__ v)
{
    const int idx = (blockIdx.x * 256 + threadIdx.x) * 4;
    const int u = idx >> 1;
    {
        float4 a = *(const float4*)(k + idx);
        float4 s = *(const float4*)(ks + idx);
        a.x += s.x; a.y += s.y; a.z += s.z; a.w += s.w;
        unsigned h0, h1, l0, l1; split4(a, h0, h1, l0, l1);
        *(uint2*)&khi_g[u] = make_uint2(h0, h1);
        *(uint2*)&klo_g[u] = make_uint2(l0, l1);
    }
    {
        float4 x = *(const float4*)(v + idx);
        __half2 H0 = __floats2half2_rn(x.x, x.y);
        __half2 H1 = __floats2half2_rn(x.z, x.w);
        *(uint2*)&vh_g[u] = make_uint2(*(unsigned*)&H0, *(unsigned*)&H1);
    }
}

__global__ __launch_bounds__(THREADS, 3)
void sdpa_fused_kernel(const float* __restrict__ q,
                       const float* __restrict__ qs,
                       float* __restrict__ out,
                       float* __restrict__ attn,
                       float* __restrict__ score)
{
    extern __shared__ char smb[];
    const unsigned sb = (unsigned)__cvta_generic_to_shared(smb);
    const int tid  = threadIdx.x;
    const int wid  = tid >> 5;
    const int lane = tid & 31;
    const int b    = blockIdx.y;
    const int row0 = blockIdx.x * Mr;
    const size_t bND = (size_t)b * Nn * Dn;
    const size_t bNN = (size_t)b * Nn * Nn;

    float* spart = (float*)(smb + SM_SPART);
    float* sinv  = (float*)(smb + SM_SINV);
    float* red   = (float*)(smb + RED);

    const int mq2 = wid >> 1;   // 0..3 : 16 query rows each
    const int nq  = wid & 1;    // 0..1 : 32 keys each
    const int lq = lane >> 2;   // 0..7
    const int lr = lane & 3;    // 0..3

    float sreg[2] = {0.f, 0.f};
    float oacc[8][4];
    #pragma unroll
    for (int dn = 0; dn < 8; dn++)
        #pragma unroll
        for (int i = 0; i < 4; i++) oacc[dn][i] = 0.f;

    // ---- per-thread fill chunks (pure 16B copies, padded rows) ----
    const int cr  = tid >> 3;            // 0..31
    const int cp_ = tid & 7;
    const unsigned dst_off = (unsigned)(cr * (SA * 2) + cp_ * 16);
    const int src_off = cr * 32 + cp_ * 4;

    auto fillS = [&](int kbf, int sf) {
        const unsigned stK = sb + STAGE0 + (unsigned)sf * STAGESZ;
        const int gb = (b * Nn + kbf * NB) * 32;
        #pragma unroll
        for (int it = 0; it < 2; it++) {
            const unsigned d = stK + dst_off + (unsigned)it * 32 * (SA * 2);
            const int s = gb + src_off + it * 32 * 32;
            cpa16(d,         khi_g + s);
            cpa16(d + 9216,  klo_g + s);
            cpa16(d + 18432, vh_g  + s);
        }
    };

    // ---- prologue: stage0/1 async fills + in-kernel Q convert (overlapped) ----
    fillS(0, 0);
    CP_COMMIT();
    fillS(1, 1);
    CP_COMMIT();
    {
        // Qf = (q + q_sem) * 0.125 -> bf16 hi/lo [64][SA] via LDG+STS
        const float* qp  = q  + bND + (size_t)row0 * Dn;
        const float* qsp = qs + bND + (size_t)row0 * Dn;
        #pragma unroll
        for (int it = 0; it < 4; it++) {
            int idx = (tid + it * THREADS) * 4;
            float4 a = *(const float4*)(qp + idx);
            float4 s0 = *(const float4*)(qsp + idx);
            a.x = (a.x + s0.x) * 0.125f; a.y = (a.y + s0.y) * 0.125f;
            a.z = (a.z + s0.z) * 0.125f; a.w = (a.w + s0.w) * 0.125f;
            int r = idx >> 6, d = idx & 63;
            unsigned h0, h1, l0, l1; split4(a, h0, h1, l0, l1);
            char* p = smb + Q_HI + (r * SA + d) * 2;
            *(uint2*)p = make_uint2(h0, h1);
            *(uint2*)(p + (Q_LO - Q_HI)) = make_uint2(l0, l1);
        }
    }
    CP_WAIT1();
    __syncthreads();

    const unsigned a_lane = (unsigned)(((lane & 15) * SA + (lane >> 4) * 8) * 2);
    const unsigned b_lane = (unsigned)(((((lane >> 4) << 3) + (lane & 7)) * SA
                                        + (((lane >> 3) & 1) << 3)) * 2);
    const unsigned aS0 = sb + Q_HI + (unsigned)((mq2 * 16) * SA * 2) + a_lane;
    const unsigned vb_lane = (unsigned)(((lane & 15) * SA + (lane >> 4) * 8) * 2);

    for (int kb = 0; kb < Nn / NB; kb++) {
        const unsigned stK = sb + STAGE0 + (unsigned)(kb & 1) * STAGESZ;

        // ---- S-GEMM: 16 rows x 32 keys (bf16 3-term), scores pre-scaled ----
        float acc[4][4];
        #pragma unroll
        for (int nf = 0; nf < 4; nf++)
            #pragma unroll
            for (int i = 0; i < 4; i++) acc[nf][i] = 0.f;

        const unsigned bS0 = stK + (unsigned)((nq * 32) * SA * 2) + b_lane;
        const unsigned bS1 = bS0 + (unsigned)(16 * SA * 2);
        #pragma unroll
        for (int ksi = 0; ksi < 4; ksi++) {
            const unsigned ko = (unsigned)(ksi * 32);
            unsigned ah[4], al[4], bh[8], bl[8];
            ldsm4(ah, aS0 + ko);
            ldsm4(al, aS0 + ko + (Q_LO - Q_HI));
            ldsm4(bh,     bS0 + ko);
            ldsm4(bh + 4, bS1 + ko);
            ldsm4(bl,     bS0 + ko + 9216);
            ldsm4(bl + 4, bS1 + ko + 9216);
            #pragma unroll
            for (int nf = 0; nf < 4; nf++) {
                mma16816(acc[nf], ah, bh + nf * 2);
                mma16816(acc[nf], ah, bl + nf * 2);
                mma16816(acc[nf], al, bh + nf * 2);
            }
        }

        // ---- exp -> E frags (fp16), row sums ----
        unsigned ahv[2][4];
        #pragma unroll
        for (int nf = 0; nf < 4; nf++) {
            float e0 = __expf(acc[nf][0] - ESH), e1 = __expf(acc[nf][1] - ESH);
            float e2 = __expf(acc[nf][2] - ESH), e3 = __expf(acc[nf][3] - ESH);
            sreg[0] += e0 + e1;
            sreg[1] += e2 + e3;
            __half2 ep0 = __floats2half2_rn(e0, e1);
            __half2 ep1 = __floats2half2_rn(e2, e3);
            const int kf = nf >> 1, pos = (nf & 1) * 2;
            ahv[kf][pos]     = *(unsigned*)&ep0;
            ahv[kf][pos + 1] = *(unsigned*)&ep1;
        }

        // ---- PV (fp16): 32 keys x 64 d-cols ----
        #pragma unroll
        for (int kf = 0; kf < 2; kf++) {
            const unsigned bVb = stK + 18432u
                + (unsigned)((nq * 32 + kf * 16) * SA * 2) + vb_lane;
            #pragma unroll
            for (int dn = 0; dn < 4; dn++) {
                unsigned bh[4];
                ldsm4t(bh, bVb + dn * 32);
                mma16816h(oacc[dn * 2 + 0], ahv[kf], bh + 0);
                mma16816h(oacc[dn * 2 + 1], ahv[kf], bh + 2);
            }
        }

        // ---- score STG last (drains behind MMA latency) ----
        #pragma unroll
        for (int nf = 0; nf < 4; nf++) {
            const int r0 = row0 + mq2 * 16 + lq;
            const int cc = kb * NB + nq * 32 + nf * 8 + lr * 2;
            float* g0 = score + bNN + (size_t)r0 * Nn + cc;
            *(float2*)g0 = make_float2(acc[nf][0], acc[nf][1]);
            *(float2*)(g0 + (size_t)8 * Nn) = make_float2(acc[nf][2], acc[nf][3]);
        }

        __syncthreads();   // all reads of stage kb done
        if (kb + 2 < Nn / NB) fillS(kb + 2, kb & 1);
        CP_COMMIT();
        CP_WAIT1();        // fill(kb+1) complete
        __syncthreads();
    }

    // ---- combine row sums + stage partial O ----
    #pragma unroll
    for (int i = 0; i < 2; i++) {
        sreg[i] += __shfl_xor_sync(0xffffffffu, sreg[i], 1);
        sreg[i] += __shfl_xor_sync(0xffffffffu, sreg[i], 2);
    }
    if (lr == 0) {
        spart[nq * 64 + mq2 * 16 + lq]     = sreg[0];
        spart[nq * 64 + mq2 * 16 + 8 + lq] = sreg[1];
    }
    {
        const int rl = mq2 * 16 + lq;
        #pragma unroll
        for (int dn = 0; dn < 8; dn++) {
            const int cl = dn * 8 + 2 * lr;
            float* p0 = red + ((size_t)nq * 64 + rl) * RSTR + cl;
            *(float2*)p0 = make_float2(oacc[dn][0], oacc[dn][1]);
            *(float2*)(p0 + 8 * RSTR) = make_float2(oacc[dn][2], oacc[dn][3]);
        }
    }
    __syncthreads();

    // ---- reduce 2 slices, scale by 1/rowsum, write O; publish sinv ----
    {
        const int r = tid >> 2;
        const int cb = (tid & 3) * 16;
        const float iv = 1.0f / (spart[r] + spart[64 + r]);
        if ((tid & 3) == 0) sinv[r] = iv;
        float* orow = out + bND + (size_t)(row0 + r) * Dn;
        #pragma unroll
        for (int g = 0; g < 4; g++) {
            const int c = cb + g * 4;
            float4 s0 = *(float4*)(red + (size_t)r * RSTR + c);
            float4 s1 = *(float4*)(red + ((size_t)64 + r) * RSTR + c);
            float4 o;
            o.x = (s0.x + s1.x) * iv;
            o.y = (s0.y + s1.y) * iv;
            o.z = (s0.z + s1.z) * iv;
            o.w = (s0.w + s1.w) * iv;
            *(float4*)(orow + c) = o;
        }
    }
    __syncthreads();

    // ---- coalesced attn rescale: attn = exp(score - ESH) * inv ----
    #pragma unroll
    for (int rr = 0; rr < 8; rr++) {
        const int r = rr * 8 + wid;
        const float iv = sinv[r];
        const float* srow = score + bNN + (size_t)(row0 + r) * Nn;
        float* arow = attn + bNN + (size_t)(row0 + r) * Nn;
        #pragma unroll
        for (int j = 0; j < 8; j++) {
            float4 x = __ldcs((const float4*)(srow + j * 128 + lane * 4));
            float4 p;
            p.x = __expf(x.x - ESH) * iv; p.y = __expf(x.y - ESH) * iv;
            p.z = __expf(x.z - ESH) * iv; p.w = __expf(x.w - ESH) * iv;
            __stwt((float4*)(arow + j * 128 + lane * 4), p);
        }
    }
}

extern "C" void kernel_launch(void* const* d_in, const int* in_sizes, int n_in,
                              void* d_out, int out_size) {
    const float* q  = (const float*)d_in[0];
    const float* k  = (const float*)d_in[1];
    const float* v  = (const float*)d_in[2];
    const float* qs = (const float*)d_in[3];
    const float* ks = (const float*)d_in[4];

    float* out   = (float*)d_out;
    float* attn  = out  + (size_t)Bn * Nn * Dn;
    float* score = attn + (size_t)Bn * Nn * Nn;

    prep_kernel<<<(Bn * Nn * Dn) / (256 * 4), 256>>>(k, ks, v);

    cudaFuncSetAttribute(sdpa_fused_kernel,
                         cudaFuncAttributeMaxDynamicSharedMemorySize, SM_TOTAL);
    dim3 grid(Nn / Mr, Bn);
    sdpa_fused_kernel<<<grid, THREADS, SM_TOTAL>>>(q, qs, out, attn, score);
}